// round 14
// baseline (speedup 1.0000x reference)
#include <cuda_runtime.h>
#include <cstdint>

#define EMB     300
#define EMB4    75
#define TASKS   12
#define ROWB    16                      // rows per pipeline chunk (19200 B)
#define NBUF    3
#define THREADS 160                     // 5 warps; 150 loader lanes
#define NCTA    444                     // 3 CTAs/SM x 148 SMs = one wave
#define IDS_CAP 1024                    // smem id-segment (multiple of ROWB)

__device__ __forceinline__ void facc(float4& a, const float4 v) {
    a.x += v.x; a.y += v.y; a.z += v.z; a.w += v.w;
}

// ---------------------------------------------------------------------------
// Single kernel, fully decoupled CTAs (no table, no grid barrier):
//   1) 160-thread parallel lower_bound finds this CTA's row range [base,end)
//   2) batch ids staged in a 4KB smem segment; graph boundaries detected from
//      id changes during consumption
//   3) round-11 pool loop: cp.async.bulk 3-stage ring, ROWB=16 chunks,
//      register head partials, warp-shfl finalize, one sync per graph
// ---------------------------------------------------------------------------
__global__ __launch_bounds__(THREADS)
void pool_fused_kernel(const float* __restrict__ x,
                       const void*  __restrict__ batch,
                       const float* __restrict__ W,
                       const float* __restrict__ b,
                       float* __restrict__ out, int N, int G) {
    __shared__ alignas(16) float4 buf[NBUF][ROWB * EMB4];
    __shared__ alignas(8)  unsigned long long mbar[NBUF];
    __shared__ alignas(16) float sh_warp[2][5 * TASKS];
    __shared__ int sh_ids[IDS_CAP];
    __shared__ int sJ;

    int t = threadIdx.x;
    const int*       b32 = (const int*)batch;
    const long long* b64 = (const long long*)batch;
    const bool is64 = (b32[N - 1] == 0);   // int64 high word of last elem == 0

    int g0 = (int)(((long long)blockIdx.x * G) / NCTA);
    int g1 = (int)(((long long)(blockIdx.x + 1) * G) / NCTA);

    // ---- parallel lower_bound(batch, v): 3 rounds, all threads converge ----
    auto lbound = [&](int v) -> int {
        int lo = 0, hi = N;
        #pragma unroll
        for (int round = 0; round < 3; ++round) {
            int len  = hi - lo;
            int step = (len + THREADS - 1) / THREADS; if (step < 1) step = 1;
            __syncthreads();
            if (t == 0) sJ = -1;
            __syncthreads();
            int pos = lo + t * step;
            if (pos < hi) {
                int idv = is64 ? (int)b64[pos] : b32[pos];
                if (idv < v) atomicMax(&sJ, t);
            }
            __syncthreads();
            int J = sJ;
            if (J < 0) { hi = lo; }
            else {
                int pj = lo + J * step;
                int nh = pj + step + 1;
                lo = pj + 1;
                if (nh < hi) hi = nh;
            }
        }
        return lo;                         // == lower bound (size <= 1 left)
    };

    int base = lbound(g0);
    int end  = lbound(g1);
    int rows_total = end - base;
    int nchunks    = (rows_total + ROWB - 1) / ROWB;

    uint32_t mb0 = (uint32_t)__cvta_generic_to_shared(&mbar[0]);
    if (t == 0) {
        #pragma unroll
        for (int s = 0; s < NBUF; ++s)
            asm volatile("mbarrier.init.shared::cta.b64 [%0], 1;"
                         :: "r"(mb0 + 8u * s) : "memory");
    }

    // ---- stage first id segment (rows [0, IDS_CAP) relative) ----
    auto load_ids = [&](int seg_start) {
        int cnt = rows_total - seg_start; if (cnt > IDS_CAP) cnt = IDS_CAP;
        for (int i = t; i < cnt; i += THREADS) {
            int r = base + seg_start + i;
            sh_ids[i] = is64 ? (int)b64[r] : b32[r];
        }
    };
    load_ids(0);
    __syncthreads();    // covers mbarrier init + sh_ids visibility

    const char* src_base = (const char*)(x + (size_t)base * EMB);
    auto issue = [&](int kk, int st) {
        int r0 = kk * ROWB;
        int rc = rows_total - r0; if (rc > ROWB) rc = ROWB;
        uint32_t bytes = (uint32_t)rc * (EMB * 4);
        uint32_t mb    = mb0 + 8u * st;
        uint32_t dst   = (uint32_t)__cvta_generic_to_shared(&buf[st][0]);
        const char* sp = src_base + (size_t)r0 * (EMB * 4);
        asm volatile("mbarrier.arrive.expect_tx.shared::cta.b64 _, [%0], %1;"
                     :: "r"(mb), "r"(bytes) : "memory");
        asm volatile("cp.async.bulk.shared::cta.global.mbarrier::complete_tx::bytes [%0], [%1], %2, [%3];"
                     :: "r"(dst), "l"(sp), "r"(bytes), "r"(mb) : "memory");
    };
    if (t == 0) {
        int pre = nchunks < (NBUF - 1) ? nchunks : (NBUF - 1);
        for (int k = 0; k < pre; ++k) issue(k, k);
    }

    int c = t % EMB4;            // float4 column
    int p = t / EMB4;            // row parity (t<150); p==2 lanes never load
    int wid = t >> 5, lane = t & 31;
    const float4* __restrict__ W4 = (const float4*)W;
    float4 acc = make_float4(0.f, 0.f, 0.f, 0.f);

    int cur_id    = (rows_total > 0) ? sh_ids[0] : g1;
    int run_start = 0;           // relative row where current graph began
    int fcnt      = 0;           // finalize counter (sh_warp parity)

    // bias for graphs before the first occurring id
    for (int gg = g0; gg < cur_id; ++gg)
        if (t < TASKS) out[(size_t)gg * TASKS + t] = __ldg(&b[t]);

    auto do_finalize = [&](int end_row, int next_id) {
        int pb = fcnt & 1;
        float inv = 1.0f / fmaxf((float)(end_row - run_start), 1.0f);
        #pragma unroll
        for (int task = 0; task < TASKS; ++task) {
            float4 w4 = __ldg(&W4[task * EMB4 + c]);
            float pz = acc.x * w4.x + acc.y * w4.y + acc.z * w4.z + acc.w * w4.w;
            #pragma unroll
            for (int o = 16; o; o >>= 1) pz += __shfl_xor_sync(0xffffffffu, pz, o);
            if (lane == 0) sh_warp[pb][wid * TASKS + task] = pz;
        }
        __syncthreads();
        if (t < TASKS) {
            const float* sw = &sh_warp[pb][0];
            float a = sw[t] + sw[TASKS + t] + sw[2 * TASKS + t]
                    + sw[3 * TASKS + t] + sw[4 * TASKS + t];
            out[(size_t)cur_id * TASKS + t] = a * inv + __ldg(&b[t]);
        }
        // bias for skipped (empty) graphs between cur_id and next_id
        for (int gg = cur_id + 1; gg < next_id; ++gg)
            if (t < TASKS) out[(size_t)gg * TASKS + t] = __ldg(&b[t]);
        acc = make_float4(0.f, 0.f, 0.f, 0.f);
        run_start = end_row;
        cur_id = next_id;
        ++fcnt;
    };

    int cs = 0, cph = 0;                 // consumer ring cursor
    int ps = (NBUF - 1) % NBUF;          // producer stage for chunk k+NBUF-1

    for (int k = 0; k < nchunks; ++k) {
        int rbase = k * ROWB;

        // id-segment refill (aligned: IDS_CAP % ROWB == 0); prev chunk's
        // trailing sync guarantees old ids no longer read
        if (rbase > 0 && (rbase & (IDS_CAP - 1)) == 0) {
            load_ids(rbase);
            __syncthreads();
        }

        uint32_t mb = mb0 + 8u * cs;
        uint32_t done;
        asm volatile("{\n\t.reg .pred p;\n\t"
                     "mbarrier.try_wait.parity.acquire.cta.shared::cta.b64 p, [%1], %2;\n\t"
                     "selp.b32 %0, 1, 0, p;\n\t}"
                     : "=r"(done) : "r"(mb), "r"((uint32_t)cph) : "memory");
        while (!done) {
            asm volatile("{\n\t.reg .pred p;\n\t"
                         "mbarrier.try_wait.parity.acquire.cta.shared::cta.b64 p, [%1], %2, 0x989680;\n\t"
                         "selp.b32 %0, 1, 0, p;\n\t}"
                         : "=r"(done) : "r"(mb), "r"((uint32_t)cph) : "memory");
        }

        // refill (NBUF-1)-ahead: target stage was released at iter k-1's sync
        if (t == 0 && k + (NBUF - 1) < nchunks) {
            asm volatile("fence.proxy.async.shared::cta;" ::: "memory");
            issue(k + (NBUF - 1), ps);
        }

        int rend = rbase + ROWB; if (rend > rows_total) rend = rows_total;
        const float4* bp = &buf[cs][0];

        // boundary exactly at previous chunk end: finalize before consuming
        int id_first = sh_ids[rbase & (IDS_CAP - 1)];
        if (id_first != cur_id) do_finalize(rbase, id_first);

        int id_last = sh_ids[(rend - 1) & (IDS_CAP - 1)];
        if (id_first == id_last && rend == rbase + ROWB) {
            // fast path: whole (full) chunk inside current graph
            if (t < 150) {
                #pragma unroll
                for (int r = 0; r < ROWB; r += 2)
                    facc(acc, bp[(r + p) * EMB4 + c]);
            }
        } else {
            int pos = rbase;
            while (pos < rend) {
                int e = pos;
                while (e < rend && sh_ids[e & (IDS_CAP - 1)] == cur_id) ++e;
                if (t < 150) {
                    for (int r = pos; r < e; ++r) {
                        if (((r - rbase) & 1) == p)
                            facc(acc, bp[(r - rbase) * EMB4 + c]);
                    }
                }
                if (e < rend) do_finalize(e, sh_ids[e & (IDS_CAP - 1)]);
                pos = e;
            }
        }
        __syncthreads();   // stage cs consumed -> refillable next iteration

        if (++cs == NBUF) { cs = 0; cph ^= 1; }
        if (++ps == NBUF) { ps = 0; }
    }

    if (rows_total > 0) {
        do_finalize(rows_total, g1);     // closes last graph; bias-fills to g1
    } else {
        for (int gg = g0; gg < g1; ++gg)
            if (t < TASKS) out[(size_t)gg * TASKS + t] = __ldg(&b[t]);
    }
}

// ---------------------------------------------------------------------------
extern "C" void kernel_launch(void* const* d_in, const int* in_sizes, int n_in,
                              void* d_out, int out_size) {
    const float* x     = (const float*)d_in[0];
    const void*  batch = d_in[1];
    const float* W     = (const float*)d_in[2];
    const float* b     = (const float*)d_in[3];
    float*       out   = (float*)d_out;

    int N = in_sizes[1];
    int G = out_size / TASKS;

    pool_fused_kernel<<<NCTA, THREADS>>>(x, batch, W, b, out, N, G);
}

// round 15
// speedup vs baseline: 1.1248x; 1.1248x over previous
#include <cuda_runtime.h>
#include <cstdint>

#define EMB     300
#define EMB4    75
#define TASKS   12
#define ROWB    16                      // rows per pipeline chunk (19200 B)
#define NBUF    3
#define THREADS 160                     // 5 warps; 150 loader lanes
#define NCTA    444                     // 3 CTAs/SM x 148 SMs = one wave

__device__ int g_starts[16385 * 2];

// ---------------------------------------------------------------------------
// Vectorized starts fill: each thread handles 8 consecutive batch elements
// (int4 loads). starts[g] = lower_bound(sorted batch, g).
// int32/int64 detected via word[N-1] (int64 high word == 0).
// Triggers programmatic launch completion so the pool kernel's prologue
// overlaps with this kernel's tail.
// ---------------------------------------------------------------------------
__global__ void starts_kernel(const void* __restrict__ batch, int N, int G) {
    int base = (blockIdx.x * blockDim.x + threadIdx.x) * 8;
    if (base < N) {
        const int* b32 = (const int*)batch;
        bool is64 = (b32[N - 1] == 0);

        int cnt = N - base; if (cnt > 8) cnt = 8;
        int ids[8];
        if (is64) {
            const long long* b64 = (const long long*)batch;
            if (cnt == 8) {
                const int4* p = (const int4*)(b64 + base);
                int4 v0 = p[0], v1 = p[1], v2 = p[2], v3 = p[3];
                ids[0] = v0.x; ids[1] = v0.z; ids[2] = v1.x; ids[3] = v1.z;
                ids[4] = v2.x; ids[5] = v2.z; ids[6] = v3.x; ids[7] = v3.z;
            } else {
                for (int j = 0; j < cnt; ++j) ids[j] = (int)b64[base + j];
            }
        } else {
            if (cnt == 8) {
                const int4* p = (const int4*)(b32 + base);
                int4 v0 = p[0], v1 = p[1];
                ids[0] = v0.x; ids[1] = v0.y; ids[2] = v0.z; ids[3] = v0.w;
                ids[4] = v1.x; ids[5] = v1.y; ids[6] = v1.z; ids[7] = v1.w;
            } else {
                for (int j = 0; j < cnt; ++j) ids[j] = b32[base + j];
            }
        }

        int prev;
        if (base == 0) prev = -1;
        else prev = is64 ? (int)((const long long*)batch)[base - 1] : b32[base - 1];

        #pragma unroll
        for (int j = 0; j < 8; ++j) {
            if (j >= cnt) break;
            int cur = ids[j];
            for (int g = prev + 1; g <= cur; ++g)
                if (g >= 0 && g <= G) g_starts[g] = base + j;
            prev = cur;
        }
        if (base + cnt == N) {
            for (int g = prev + 1; g <= G; ++g) g_starts[g] = N;
        }
    }
#if defined(__CUDA_ARCH__) && (__CUDA_ARCH__ >= 900)
    cudaTriggerProgrammaticLaunchCompletion();
#endif
}

__device__ __forceinline__ void facc(float4& a, const float4 v) {
    a.x += v.x; a.y += v.y; a.z += v.z; a.w += v.w;
}

// ---------------------------------------------------------------------------
// Persistent single-wave CTA over a contiguous graph range (round-11 proven
// design): one continuous cp.async.bulk stream, 3-stage ring of 16-row
// chunks. Finalize: per-thread head partial -> warp shfl -> 60-float smem ->
// ONE sync -> 12 stores. PDL: g_starts-independent prologue runs before
// cudaGridDependencySynchronize().
// ---------------------------------------------------------------------------
__global__ __launch_bounds__(THREADS)
void pool_pers_kernel(const float* __restrict__ x,
                      const float* __restrict__ W,
                      const float* __restrict__ b,
                      float* __restrict__ out, int G) {
    __shared__ alignas(16) float4 buf[NBUF][ROWB * EMB4];
    __shared__ alignas(8)  unsigned long long mbar[NBUF];
    __shared__ alignas(16) float sh_warp[2][5 * TASKS];

    int t = threadIdx.x;
    int g0 = (int)(((long long)blockIdx.x * G) / NCTA);
    int g1 = (int)(((long long)(blockIdx.x + 1) * G) / NCTA);
    int gcnt = g1 - g0;

    // ---- g_starts-independent prologue (overlaps with starts_kernel) ----
    uint32_t mb0 = (uint32_t)__cvta_generic_to_shared(&mbar[0]);
    if (t == 0) {
        #pragma unroll
        for (int s = 0; s < NBUF; ++s)
            asm volatile("mbarrier.init.shared::cta.b64 [%0], 1;"
                         :: "r"(mb0 + 8u * s) : "memory");
    }
    __syncthreads();

#if defined(__CUDA_ARCH__) && (__CUDA_ARCH__ >= 900)
    cudaGridDependencySynchronize();    // g_starts now complete + visible
#endif
    if (gcnt <= 0) return;

    int base       = g_starts[g0];
    int rows_total = g_starts[g1] - base;
    int nchunks    = (rows_total + ROWB - 1) / ROWB;

    const char* src_base = (const char*)(x + (size_t)base * EMB);

    auto issue = [&](int kk, int st) {
        int r0 = kk * ROWB;
        int rc = rows_total - r0; if (rc > ROWB) rc = ROWB;
        uint32_t bytes = (uint32_t)rc * (EMB * 4);
        uint32_t mb    = mb0 + 8u * st;
        uint32_t dst   = (uint32_t)__cvta_generic_to_shared(&buf[st][0]);
        const char* sp = src_base + (size_t)r0 * (EMB * 4);
        asm volatile("mbarrier.arrive.expect_tx.shared::cta.b64 _, [%0], %1;"
                     :: "r"(mb), "r"(bytes) : "memory");
        asm volatile("cp.async.bulk.shared::cta.global.mbarrier::complete_tx::bytes [%0], [%1], %2, [%3];"
                     :: "r"(dst), "l"(sp), "r"(bytes), "r"(mb) : "memory");
    };

    if (t == 0) {
        int pre = nchunks < (NBUF - 1) ? nchunks : (NBUF - 1);
        for (int k = 0; k < pre; ++k) issue(k, k);
    }

    int c = t % EMB4;            // float4 column
    int p = t / EMB4;            // row parity (t<150)
    int wid = t >> 5, lane = t & 31;
    const float4* __restrict__ W4 = (const float4*)W;
    float4 acc = make_float4(0.f, 0.f, 0.f, 0.f);

    int gi = 0;
    int gstart = 0;
    int nb = g_starts[g0 + 1] - base;

    auto do_finalize = [&](int end_row) {
        int pb = gi & 1;
        float inv = 1.0f / fmaxf((float)(end_row - gstart), 1.0f);
        #pragma unroll
        for (int task = 0; task < TASKS; ++task) {
            float4 w4 = __ldg(&W4[task * EMB4 + c]);
            float pz = acc.x * w4.x + acc.y * w4.y + acc.z * w4.z + acc.w * w4.w;
            #pragma unroll
            for (int o = 16; o; o >>= 1) pz += __shfl_xor_sync(0xffffffffu, pz, o);
            if (lane == 0) sh_warp[pb][wid * TASKS + task] = pz;
        }
        __syncthreads();
        if (t < TASKS) {
            const float* sw = &sh_warp[pb][0];
            float a = sw[t] + sw[TASKS + t] + sw[2 * TASKS + t]
                    + sw[3 * TASKS + t] + sw[4 * TASKS + t];
            out[(size_t)(g0 + gi) * TASKS + t] = a * inv + __ldg(&b[t]);
        }
        acc = make_float4(0.f, 0.f, 0.f, 0.f);
        gstart = end_row;
        ++gi;
        nb = (gi < gcnt) ? g_starts[g0 + gi + 1] - base : 0x7fffffff;
    };

    int cs = 0, cph = 0;                 // consumer ring cursor
    int ps = (NBUF - 1) % NBUF;          // producer stage for chunk k+NBUF-1

    for (int k = 0; k < nchunks; ++k) {
        uint32_t mb = mb0 + 8u * cs;
        uint32_t ph = (uint32_t)cph;

        uint32_t done;
        asm volatile("{\n\t.reg .pred p;\n\t"
                     "mbarrier.try_wait.parity.acquire.cta.shared::cta.b64 p, [%1], %2;\n\t"
                     "selp.b32 %0, 1, 0, p;\n\t}"
                     : "=r"(done) : "r"(mb), "r"(ph) : "memory");
        while (!done) {
            asm volatile("{\n\t.reg .pred p;\n\t"
                         "mbarrier.try_wait.parity.acquire.cta.shared::cta.b64 p, [%1], %2, 0x989680;\n\t"
                         "selp.b32 %0, 1, 0, p;\n\t}"
                         : "=r"(done) : "r"(mb), "r"(ph) : "memory");
        }

        // refill (NBUF-1)-ahead: its target stage was consumed at iter k-1
        // and released by that iteration's trailing __syncthreads.
        if (t == 0 && k + (NBUF - 1) < nchunks) {
            asm volatile("fence.proxy.async.shared::cta;" ::: "memory");
            issue(k + (NBUF - 1), ps);
        }

        int rbase = k * ROWB;
        int rend  = rbase + ROWB; if (rend > rows_total) rend = rows_total;
        const float4* bp = &buf[cs][0];

        if (nb >= rend && rend == rbase + ROWB) {
            // fast path: whole (full) chunk inside current graph
            if (t < 150) {
                #pragma unroll
                for (int r = 0; r < ROWB; r += 2)
                    facc(acc, bp[(r + p) * EMB4 + c]);
            }
        } else {
            int pos = rbase;
            while (pos < rend) {
                int stop = nb < rend ? nb : rend;
                if (t < 150) {
                    for (int r = pos; r < stop; ++r) {
                        if (((r - rbase) & 1) == p)
                            facc(acc, bp[(r - rbase) * EMB4 + c]);
                    }
                }
                if (stop == nb) do_finalize(nb);
                pos = stop;
            }
        }
        __syncthreads();   // stage cs consumed -> refillable next iteration

        if (++cs == NBUF) { cs = 0; cph ^= 1; }
        if (++ps == NBUF) { ps = 0; }
    }

    // graph whose boundary coincides with the final chunk end is still open
    if (gi < gcnt) do_finalize(rows_total);

    // remaining graphs are empty: mean = 0 -> out = bias
    while (gi < gcnt) {
        if (t < TASKS) out[(size_t)(g0 + gi) * TASKS + t] = __ldg(&b[t]);
        ++gi;
    }
}

// ---------------------------------------------------------------------------
extern "C" void kernel_launch(void* const* d_in, const int* in_sizes, int n_in,
                              void* d_out, int out_size) {
    const float* x     = (const float*)d_in[0];
    const void*  batch = d_in[1];
    const float* W     = (const float*)d_in[2];
    const float* b     = (const float*)d_in[3];
    float*       out   = (float*)d_out;

    int N = in_sizes[1];
    int G = out_size / TASKS;

    int nthreads = (N + 7) / 8;
    starts_kernel<<<(nthreads + 255) / 256, 256>>>(batch, N, G);

    // Pool kernel with Programmatic Dependent Launch: launch overlaps the
    // starts_kernel tail; correctness guaranteed by gridDependencySynchronize.
    cudaLaunchConfig_t cfg = {};
    cfg.gridDim  = dim3(NCTA, 1, 1);
    cfg.blockDim = dim3(THREADS, 1, 1);
    cfg.dynamicSmemBytes = 0;
    cfg.stream = 0;
    cudaLaunchAttribute attrs[1];
    attrs[0].id = cudaLaunchAttributeProgrammaticStreamSerialization;
    attrs[0].val.programmaticStreamSerializationAllowed = 1;
    cfg.attrs = attrs;
    cfg.numAttrs = 1;
    cudaLaunchKernelEx(&cfg, pool_pers_kernel, x, W, b, out, G);
}